// round 1
// baseline (speedup 1.0000x reference)
#include <cuda_runtime.h>
#include <math.h>

// Problem constants
constexpr int B_  = 2;
constexpr int S_  = 2048;
constexpr int H_  = 1024;
constexpr int NH_ = 16;
constexpr int HD_ = 64;
constexpr int M_  = B_ * S_;   // 4096 rows for the projections
constexpr int K_  = H_;        // 1024 reduction dim

// Scratch (device globals — no allocation allowed)
// g_q, g_k stored d-major: [b, h, d, s]  (so attention loads need no transpose)
// g_v stored               [b, h, s, d]
// g_att stored             [b, s, h*HD + d]  == [M, H]
__device__ float g_q[(size_t)B_ * NH_ * HD_ * S_];
__device__ float g_k[(size_t)B_ * NH_ * HD_ * S_];
__device__ float g_v[(size_t)B_ * NH_ * S_ * HD_];
__device__ float g_att[(size_t)B_ * S_ * H_];

// ---------------------------------------------------------------------------
// GEMM:  C[m,n] = sum_k A[m,k] * W[n,k] + bias[n]      (A: [M,K], W: [N,K])
// mode 0: A=Aext, C=g_q  (qk layout [b,h,d,s])
// mode 1: A=Aext, C=g_k  (qk layout)
// mode 2: A=Aext, C=g_v  (v layout [b,h,s,d])
// mode 3: A=g_att, C=Cext (plain [M,H])
// ---------------------------------------------------------------------------
__global__ void __launch_bounds__(256) gemm_nt(const float* __restrict__ Aext,
                                               const float* __restrict__ W,
                                               const float* __restrict__ bias,
                                               float* __restrict__ Cext,
                                               int mode)
{
    constexpr int BM = 64, BN = 64, BK = 16, LDP = BM + 4; // 68
    __shared__ float As[BK][LDP];
    __shared__ float Bs[BK][LDP];

    const float* A = (mode == 3) ? g_att : Aext;

    const int tid = threadIdx.x;
    const int tx = tid & 15;        // N direction
    const int ty = tid >> 4;        // M direction
    const int m0 = blockIdx.y * BM;
    const int n0 = blockIdx.x * BN;
    const int lrow = tid >> 2;          // 0..63
    const int lkg  = (tid & 3) * 4;     // 0,4,8,12

    float acc[4][4];
#pragma unroll
    for (int i = 0; i < 4; i++)
#pragma unroll
        for (int j = 0; j < 4; j++) acc[i][j] = 0.0f;

    for (int k0 = 0; k0 < K_; k0 += BK) {
        float4 av = *(const float4*)&A[(size_t)(m0 + lrow) * K_ + k0 + lkg];
        float4 wv = *(const float4*)&W[(size_t)(n0 + lrow) * K_ + k0 + lkg];
        As[lkg + 0][lrow] = av.x; As[lkg + 1][lrow] = av.y;
        As[lkg + 2][lrow] = av.z; As[lkg + 3][lrow] = av.w;
        Bs[lkg + 0][lrow] = wv.x; Bs[lkg + 1][lrow] = wv.y;
        Bs[lkg + 2][lrow] = wv.z; Bs[lkg + 3][lrow] = wv.w;
        __syncthreads();
#pragma unroll
        for (int k = 0; k < BK; k++) {
            float a[4], b[4];
            *(float4*)a = *(const float4*)&As[k][ty * 4];
            *(float4*)b = *(const float4*)&Bs[k][tx * 4];
#pragma unroll
            for (int i = 0; i < 4; i++)
#pragma unroll
                for (int j = 0; j < 4; j++)
                    acc[i][j] = fmaf(a[i], b[j], acc[i][j]);
        }
        __syncthreads();
    }

    float bi[4];
    *(float4*)bi = *(const float4*)&bias[n0 + tx * 4];

#pragma unroll
    for (int i = 0; i < 4; i++) {
        const int m = m0 + ty * 4 + i;
        const int n = n0 + tx * 4;
        float4 r = make_float4(acc[i][0] + bi[0], acc[i][1] + bi[1],
                               acc[i][2] + bi[2], acc[i][3] + bi[3]);
        const int b = m >> 11;            // m / S_
        const int s = m & (S_ - 1);
        const int h = n >> 6;             // n / HD_
        const int d = n & 63;
        if (mode == 0 || mode == 1) {     // [b,h,d,s] scatter (stride-S_ stores)
            float* C = (mode == 0) ? g_q : g_k;
            size_t o = ((size_t)(b * NH_ + h) * HD_ + d) * S_ + s;
            C[o] = r.x; C[o + S_] = r.y; C[o + 2 * S_] = r.z; C[o + 3 * S_] = r.w;
        } else if (mode == 2) {           // [b,h,s,d]
            size_t o = ((size_t)(b * NH_ + h) * S_ + s) * HD_ + d;
            *(float4*)&g_v[o] = r;
        } else {                          // plain [M, H]
            *(float4*)&Cext[(size_t)m * H_ + n] = r;
        }
    }
}

// ---------------------------------------------------------------------------
// RoPE in-place on g_q and g_k (both in [b,h,d,s] layout).
// q'[d]    = q[d]*cos[s,d]    - q[d+32]*sin[s,d]
// q'[d+32] = q[d+32]*cos[s,d+32] + q[d]*sin[s,d+32]
// One thread per (bh, d<32, s) pair handles both q and k.
// ---------------------------------------------------------------------------
__global__ void __launch_bounds__(256) rope_kernel(const float* __restrict__ cosb,
                                                   const float* __restrict__ sinb)
{
    const int idx = blockIdx.x * blockDim.x + threadIdx.x; // B_*NH_*32*S_ threads
    const int s  = idx & (S_ - 1);
    const int d  = (idx >> 11) & 31;
    const int bh = idx >> 16;
    const float c0 = cosb[s * HD_ + d];
    const float s0 = sinb[s * HD_ + d];
    const float c1 = cosb[s * HD_ + d + 32];
    const float s1 = sinb[s * HD_ + d + 32];
    const size_t i0 = ((size_t)bh * HD_ + d) * S_ + s;
    const size_t i1 = i0 + (size_t)32 * S_;

    float q0 = g_q[i0], q1 = g_q[i1];
    g_q[i0] = q0 * c0 - q1 * s0;
    g_q[i1] = q1 * c1 + q0 * s1;
    float k0 = g_k[i0], k1 = g_k[i1];
    g_k[i0] = k0 * c0 - k1 * s0;
    g_k[i1] = k1 * c1 + k0 * s1;
}

// ---------------------------------------------------------------------------
// Flash attention, fp32 SIMT.
// Block = one (b,h) × 64-row Q tile. 256 threads, 16x16 thread grid, 4x4 tiles.
// smem (dynamic): Qs [d][r] 64x64 | KP [64][68] (K as [d][c], reused as P [c][r])
//                 | Vs [c][d] 64x64  -> 50176 B
// ---------------------------------------------------------------------------
constexpr int ATT_SMEM_FLOATS = 64 * 64 + 64 * 68 + 64 * 64;
constexpr int ATT_SMEM_BYTES  = ATT_SMEM_FLOATS * 4;

__global__ void __launch_bounds__(256) attn_kernel(const int* __restrict__ mask)
{
    extern __shared__ float sm[];
    float* Qs = sm;                 // stride 64
    float* KP = sm + 64 * 64;       // stride 68 (272 B: 16-byte aligned rows)
    float* Vs = sm + 64 * 64 + 64 * 68; // stride 64
    __shared__ int msk[64];

    const int tid = threadIdx.x;
    const int tx = tid & 15;
    const int ty = tid >> 4;
    const int bh = blockIdx.y;
    const int b  = bh >> 4;
    const int h  = bh & 15;
    const int q0 = blockIdx.x * 64;

    const float* Qg = g_q + (size_t)bh * HD_ * S_;  // [d][s]
    const float* Kg = g_k + (size_t)bh * HD_ * S_;  // [d][s]
    const float* Vg = g_v + (size_t)bh * S_ * HD_;  // [s][d]

    // Load Q tile: Qs[d][r] = Qg[d*S + q0 + r]
#pragma unroll
    for (int t = 0; t < 4; t++) {
        int lin = tid + 256 * t;            // 0..1023
        int d = lin >> 4, sg = (lin & 15) * 4;
        *(float4*)&Qs[d * 64 + sg] = *(const float4*)&Qg[(size_t)d * S_ + q0 + sg];
    }

    float m_i[4], l_i[4], acc[4][4];
#pragma unroll
    for (int i = 0; i < 4; i++) {
        m_i[i] = -1e30f; l_i[i] = 0.0f;
#pragma unroll
        for (int j = 0; j < 4; j++) acc[i][j] = 0.0f;
    }

    for (int kt = 0; kt < S_; kt += 64) {
        __syncthreads();   // prior iteration readers of KP/Vs done
        // Load K tile [d][c] and V tile [c][d]
#pragma unroll
        for (int t = 0; t < 4; t++) {
            int lin = tid + 256 * t;
            int r = lin >> 4, g4 = (lin & 15) * 4;
            *(float4*)&KP[r * 68 + g4] = *(const float4*)&Kg[(size_t)r * S_ + kt + g4];
            *(float4*)&Vs[r * 64 + g4] = *(const float4*)&Vg[(size_t)(kt + r) * HD_ + g4];
        }
        if (tid < 64) msk[tid] = mask[b * S_ + kt + tid];
        __syncthreads();

        // S = Q . K^T  (64x64x64)
        float sv[4][4];
#pragma unroll
        for (int i = 0; i < 4; i++)
#pragma unroll
            for (int j = 0; j < 4; j++) sv[i][j] = 0.0f;
        for (int d = 0; d < 64; d++) {
            float a[4], bb[4];
            *(float4*)a  = *(const float4*)&Qs[d * 64 + ty * 4];
            *(float4*)bb = *(const float4*)&KP[d * 68 + tx * 4];
#pragma unroll
            for (int i = 0; i < 4; i++)
#pragma unroll
                for (int j = 0; j < 4; j++)
                    sv[i][j] = fmaf(a[i], bb[j], sv[i][j]);
        }

        // scale + mask
        int mk[4];
#pragma unroll
        for (int j = 0; j < 4; j++) mk[j] = msk[tx * 4 + j];
#pragma unroll
        for (int i = 0; i < 4; i++)
#pragma unroll
            for (int j = 0; j < 4; j++) {
                float v = sv[i][j] * 0.125f;        // 1/sqrt(64)
                sv[i][j] = (mk[j] == 0) ? -1e30f : v;
            }

        // online softmax per row (row owned by 16 tx lanes)
#pragma unroll
        for (int i = 0; i < 4; i++) {
            float rm = fmaxf(fmaxf(sv[i][0], sv[i][1]), fmaxf(sv[i][2], sv[i][3]));
#pragma unroll
            for (int off = 8; off > 0; off >>= 1)
                rm = fmaxf(rm, __shfl_xor_sync(0xffffffffu, rm, off, 16));
            float mn = fmaxf(m_i[i], rm);
            float corr = __expf(m_i[i] - mn);
            float rs = 0.0f;
#pragma unroll
            for (int j = 0; j < 4; j++) {
                float p = __expf(sv[i][j] - mn);
                sv[i][j] = p;
                rs += p;
            }
#pragma unroll
            for (int off = 8; off > 0; off >>= 1)
                rs += __shfl_xor_sync(0xffffffffu, rs, off, 16);
            l_i[i] = l_i[i] * corr + rs;
            m_i[i] = mn;
#pragma unroll
            for (int j = 0; j < 4; j++) acc[i][j] *= corr;
        }

        __syncthreads();   // everyone done reading KP as K
        // store P into KP as [c][r]
#pragma unroll
        for (int j = 0; j < 4; j++)
#pragma unroll
            for (int i = 0; i < 4; i++)
                KP[(tx * 4 + j) * 68 + ty * 4 + i] = sv[i][j];
        __syncthreads();

        // O += P . V   (64x64x64)
        for (int c = 0; c < 64; c++) {
            float p[4], vv[4];
            *(float4*)p  = *(const float4*)&KP[c * 68 + ty * 4];
            *(float4*)vv = *(const float4*)&Vs[c * 64 + tx * 4];
#pragma unroll
            for (int i = 0; i < 4; i++)
#pragma unroll
                for (int j = 0; j < 4; j++)
                    acc[i][j] = fmaf(p[i], vv[j], acc[i][j]);
        }
    }

    // epilogue: divide by l, write [b, s, h*HD + d]
#pragma unroll
    for (int i = 0; i < 4; i++) {
        const int s = q0 + ty * 4 + i;
        const float inv = 1.0f / l_i[i];
        float4 r = make_float4(acc[i][0] * inv, acc[i][1] * inv,
                               acc[i][2] * inv, acc[i][3] * inv);
        *(float4*)&g_att[((size_t)b * S_ + s) * H_ + h * HD_ + tx * 4] = r;
    }
}

// ---------------------------------------------------------------------------
extern "C" void kernel_launch(void* const* d_in, const int* in_sizes, int n_in,
                              void* d_out, int out_size)
{
    const float* x    = (const float*)d_in[0];
    const int*   mask = (const int*)  d_in[1];
    const float* cosb = (const float*)d_in[2];
    const float* sinb = (const float*)d_in[3];
    const float* Wq   = (const float*)d_in[4];
    const float* bq   = (const float*)d_in[5];
    const float* Wk   = (const float*)d_in[6];
    const float* bk   = (const float*)d_in[7];
    const float* Wv   = (const float*)d_in[8];
    const float* bv   = (const float*)d_in[9];
    const float* Wo   = (const float*)d_in[10];
    const float* bo   = (const float*)d_in[11];
    float* out = (float*)d_out;

    cudaFuncSetAttribute(attn_kernel,
                         cudaFuncAttributeMaxDynamicSharedMemorySize,
                         ATT_SMEM_BYTES);

    dim3 gemm_grid(H_ / 64, M_ / 64);   // (16, 64)
    gemm_nt<<<gemm_grid, 256>>>(x, Wq, bq, nullptr, 0);
    gemm_nt<<<gemm_grid, 256>>>(x, Wk, bk, nullptr, 1);
    gemm_nt<<<gemm_grid, 256>>>(x, Wv, bv, nullptr, 2);

    int rope_threads = B_ * NH_ * 32 * S_;          // 2,097,152
    rope_kernel<<<rope_threads / 256, 256>>>(cosb, sinb);

    dim3 attn_grid(S_ / 64, B_ * NH_);              // (32, 32)
    attn_kernel<<<attn_grid, 256, ATT_SMEM_BYTES>>>(mask);

    gemm_nt<<<gemm_grid, 256>>>(nullptr, Wo, bo, out, 3);
}

// round 2
// speedup vs baseline: 1.0000x; 1.0000x over previous
#include <cuda_runtime.h>
#include <math.h>

// Problem constants
constexpr int B_  = 2;
constexpr int S_  = 2048;
constexpr int H_  = 1024;
constexpr int NH_ = 16;
constexpr int HD_ = 64;
constexpr int M_  = B_ * S_;   // 4096 rows for the projections
constexpr int K_  = H_;        // 1024 reduction dim

// Scratch (device globals — no allocation allowed)
// g_q, g_k stored d-major: [b, h, d, s]  (so attention loads need no transpose)
// g_v stored               [b, h, s, d]
// g_att stored             [b, s, h*HD + d]  == [M, H]
__device__ float g_q[(size_t)B_ * NH_ * HD_ * S_];
__device__ float g_k[(size_t)B_ * NH_ * HD_ * S_];
__device__ float g_v[(size_t)B_ * NH_ * S_ * HD_];
__device__ float g_att[(size_t)B_ * S_ * H_];

// ---------------------------------------------------------------------------
// GEMM:  C[m,n] = sum_k A[m,k] * W[n,k] + bias[n]      (A: [M,K], W: [N,K])
// mode 0: A=Aext, C=g_q  (qk layout [b,h,d,s])
// mode 1: A=Aext, C=g_k  (qk layout)
// mode 2: A=Aext, C=g_v  (v layout [b,h,s,d])
// mode 3: A=g_att, C=Cext (plain [M,H])
// ---------------------------------------------------------------------------
__global__ void __launch_bounds__(256) gemm_nt(const float* __restrict__ Aext,
                                               const float* __restrict__ W,
                                               const float* __restrict__ bias,
                                               float* __restrict__ Cext,
                                               int mode)
{
    constexpr int BM = 64, BN = 64, BK = 16, LDP = BM + 4; // 68
    __shared__ float As[BK][LDP];
    __shared__ float Bs[BK][LDP];

    const float* A = (mode == 3) ? g_att : Aext;

    const int tid = threadIdx.x;
    const int tx = tid & 15;        // N direction
    const int ty = tid >> 4;        // M direction
    const int m0 = blockIdx.y * BM;
    const int n0 = blockIdx.x * BN;
    const int lrow = tid >> 2;          // 0..63
    const int lkg  = (tid & 3) * 4;     // 0,4,8,12

    float acc[4][4];
#pragma unroll
    for (int i = 0; i < 4; i++)
#pragma unroll
        for (int j = 0; j < 4; j++) acc[i][j] = 0.0f;

    for (int k0 = 0; k0 < K_; k0 += BK) {
        float4 av = *(const float4*)&A[(size_t)(m0 + lrow) * K_ + k0 + lkg];
        float4 wv = *(const float4*)&W[(size_t)(n0 + lrow) * K_ + k0 + lkg];
        As[lkg + 0][lrow] = av.x; As[lkg + 1][lrow] = av.y;
        As[lkg + 2][lrow] = av.z; As[lkg + 3][lrow] = av.w;
        Bs[lkg + 0][lrow] = wv.x; Bs[lkg + 1][lrow] = wv.y;
        Bs[lkg + 2][lrow] = wv.z; Bs[lkg + 3][lrow] = wv.w;
        __syncthreads();
#pragma unroll
        for (int k = 0; k < BK; k++) {
            float a[4], b[4];
            *(float4*)a = *(const float4*)&As[k][ty * 4];
            *(float4*)b = *(const float4*)&Bs[k][tx * 4];
#pragma unroll
            for (int i = 0; i < 4; i++)
#pragma unroll
                for (int j = 0; j < 4; j++)
                    acc[i][j] = fmaf(a[i], b[j], acc[i][j]);
        }
        __syncthreads();
    }

    float bi[4];
    *(float4*)bi = *(const float4*)&bias[n0 + tx * 4];

#pragma unroll
    for (int i = 0; i < 4; i++) {
        const int m = m0 + ty * 4 + i;
        const int n = n0 + tx * 4;
        float4 r = make_float4(acc[i][0] + bi[0], acc[i][1] + bi[1],
                               acc[i][2] + bi[2], acc[i][3] + bi[3]);
        const int b = m >> 11;            // m / S_
        const int s = m & (S_ - 1);
        const int h = n >> 6;             // n / HD_
        const int d = n & 63;
        if (mode == 0 || mode == 1) {     // [b,h,d,s] scatter (stride-S_ stores)
            float* C = (mode == 0) ? g_q : g_k;
            size_t o = ((size_t)(b * NH_ + h) * HD_ + d) * S_ + s;
            C[o] = r.x; C[o + S_] = r.y; C[o + 2 * S_] = r.z; C[o + 3 * S_] = r.w;
        } else if (mode == 2) {           // [b,h,s,d]
            size_t o = ((size_t)(b * NH_ + h) * S_ + s) * HD_ + d;
            *(float4*)&g_v[o] = r;
        } else {                          // plain [M, H]
            *(float4*)&Cext[(size_t)m * H_ + n] = r;
        }
    }
}

// ---------------------------------------------------------------------------
// RoPE in-place on g_q and g_k (both in [b,h,d,s] layout).
// q'[d]    = q[d]*cos[s,d]    - q[d+32]*sin[s,d]
// q'[d+32] = q[d+32]*cos[s,d+32] + q[d]*sin[s,d+32]
// One thread per (bh, d<32, s) pair handles both q and k.
// ---------------------------------------------------------------------------
__global__ void __launch_bounds__(256) rope_kernel(const float* __restrict__ cosb,
                                                   const float* __restrict__ sinb)
{
    const int idx = blockIdx.x * blockDim.x + threadIdx.x; // B_*NH_*32*S_ threads
    const int s  = idx & (S_ - 1);
    const int d  = (idx >> 11) & 31;
    const int bh = idx >> 16;
    const float c0 = cosb[s * HD_ + d];
    const float s0 = sinb[s * HD_ + d];
    const float c1 = cosb[s * HD_ + d + 32];
    const float s1 = sinb[s * HD_ + d + 32];
    const size_t i0 = ((size_t)bh * HD_ + d) * S_ + s;
    const size_t i1 = i0 + (size_t)32 * S_;

    float q0 = g_q[i0], q1 = g_q[i1];
    g_q[i0] = q0 * c0 - q1 * s0;
    g_q[i1] = q1 * c1 + q0 * s1;
    float k0 = g_k[i0], k1 = g_k[i1];
    g_k[i0] = k0 * c0 - k1 * s0;
    g_k[i1] = k1 * c1 + k0 * s1;
}

// ---------------------------------------------------------------------------
// Flash attention, fp32 SIMT.
// Block = one (b,h) × 64-row Q tile. 256 threads, 16x16 thread grid, 4x4 tiles.
// smem (dynamic): Qs [d][r] 64x64 | KP [64][68] (K as [d][c], reused as P [c][r])
//                 | Vs [c][d] 64x64  -> 50176 B
// ---------------------------------------------------------------------------
constexpr int ATT_SMEM_FLOATS = 64 * 64 + 64 * 68 + 64 * 64;
constexpr int ATT_SMEM_BYTES  = ATT_SMEM_FLOATS * 4;

__global__ void __launch_bounds__(256) attn_kernel(const int* __restrict__ mask)
{
    extern __shared__ float sm[];
    float* Qs = sm;                 // stride 64
    float* KP = sm + 64 * 64;       // stride 68 (272 B: 16-byte aligned rows)
    float* Vs = sm + 64 * 64 + 64 * 68; // stride 64
    __shared__ int msk[64];

    const int tid = threadIdx.x;
    const int tx = tid & 15;
    const int ty = tid >> 4;
    const int bh = blockIdx.y;
    const int b  = bh >> 4;
    const int h  = bh & 15;
    const int q0 = blockIdx.x * 64;

    const float* Qg = g_q + (size_t)bh * HD_ * S_;  // [d][s]
    const float* Kg = g_k + (size_t)bh * HD_ * S_;  // [d][s]
    const float* Vg = g_v + (size_t)bh * S_ * HD_;  // [s][d]

    // Load Q tile: Qs[d][r] = Qg[d*S + q0 + r]
#pragma unroll
    for (int t = 0; t < 4; t++) {
        int lin = tid + 256 * t;            // 0..1023
        int d = lin >> 4, sg = (lin & 15) * 4;
        *(float4*)&Qs[d * 64 + sg] = *(const float4*)&Qg[(size_t)d * S_ + q0 + sg];
    }

    float m_i[4], l_i[4], acc[4][4];
#pragma unroll
    for (int i = 0; i < 4; i++) {
        m_i[i] = -1e30f; l_i[i] = 0.0f;
#pragma unroll
        for (int j = 0; j < 4; j++) acc[i][j] = 0.0f;
    }

    for (int kt = 0; kt < S_; kt += 64) {
        __syncthreads();   // prior iteration readers of KP/Vs done
        // Load K tile [d][c] and V tile [c][d]
#pragma unroll
        for (int t = 0; t < 4; t++) {
            int lin = tid + 256 * t;
            int r = lin >> 4, g4 = (lin & 15) * 4;
            *(float4*)&KP[r * 68 + g4] = *(const float4*)&Kg[(size_t)r * S_ + kt + g4];
            *(float4*)&Vs[r * 64 + g4] = *(const float4*)&Vg[(size_t)(kt + r) * HD_ + g4];
        }
        if (tid < 64) msk[tid] = mask[b * S_ + kt + tid];
        __syncthreads();

        // S = Q . K^T  (64x64x64)
        float sv[4][4];
#pragma unroll
        for (int i = 0; i < 4; i++)
#pragma unroll
            for (int j = 0; j < 4; j++) sv[i][j] = 0.0f;
        for (int d = 0; d < 64; d++) {
            float a[4], bb[4];
            *(float4*)a  = *(const float4*)&Qs[d * 64 + ty * 4];
            *(float4*)bb = *(const float4*)&KP[d * 68 + tx * 4];
#pragma unroll
            for (int i = 0; i < 4; i++)
#pragma unroll
                for (int j = 0; j < 4; j++)
                    sv[i][j] = fmaf(a[i], bb[j], sv[i][j]);
        }

        // scale + mask
        int mk[4];
#pragma unroll
        for (int j = 0; j < 4; j++) mk[j] = msk[tx * 4 + j];
#pragma unroll
        for (int i = 0; i < 4; i++)
#pragma unroll
            for (int j = 0; j < 4; j++) {
                float v = sv[i][j] * 0.125f;        // 1/sqrt(64)
                sv[i][j] = (mk[j] == 0) ? -1e30f : v;
            }

        // online softmax per row (row owned by 16 tx lanes)
#pragma unroll
        for (int i = 0; i < 4; i++) {
            float rm = fmaxf(fmaxf(sv[i][0], sv[i][1]), fmaxf(sv[i][2], sv[i][3]));
#pragma unroll
            for (int off = 8; off > 0; off >>= 1)
                rm = fmaxf(rm, __shfl_xor_sync(0xffffffffu, rm, off, 16));
            float mn = fmaxf(m_i[i], rm);
            float corr = __expf(m_i[i] - mn);
            float rs = 0.0f;
#pragma unroll
            for (int j = 0; j < 4; j++) {
                float p = __expf(sv[i][j] - mn);
                sv[i][j] = p;
                rs += p;
            }
#pragma unroll
            for (int off = 8; off > 0; off >>= 1)
                rs += __shfl_xor_sync(0xffffffffu, rs, off, 16);
            l_i[i] = l_i[i] * corr + rs;
            m_i[i] = mn;
#pragma unroll
            for (int j = 0; j < 4; j++) acc[i][j] *= corr;
        }

        __syncthreads();   // everyone done reading KP as K
        // store P into KP as [c][r]
#pragma unroll
        for (int j = 0; j < 4; j++)
#pragma unroll
            for (int i = 0; i < 4; i++)
                KP[(tx * 4 + j) * 68 + ty * 4 + i] = sv[i][j];
        __syncthreads();

        // O += P . V   (64x64x64)
        for (int c = 0; c < 64; c++) {
            float p[4], vv[4];
            *(float4*)p  = *(const float4*)&KP[c * 68 + ty * 4];
            *(float4*)vv = *(const float4*)&Vs[c * 64 + tx * 4];
#pragma unroll
            for (int i = 0; i < 4; i++)
#pragma unroll
                for (int j = 0; j < 4; j++)
                    acc[i][j] = fmaf(p[i], vv[j], acc[i][j]);
        }
    }

    // epilogue: divide by l, write [b, s, h*HD + d]
#pragma unroll
    for (int i = 0; i < 4; i++) {
        const int s = q0 + ty * 4 + i;
        const float inv = 1.0f / l_i[i];
        float4 r = make_float4(acc[i][0] * inv, acc[i][1] * inv,
                               acc[i][2] * inv, acc[i][3] * inv);
        *(float4*)&g_att[((size_t)b * S_ + s) * H_ + h * HD_ + tx * 4] = r;
    }
}

// ---------------------------------------------------------------------------
extern "C" void kernel_launch(void* const* d_in, const int* in_sizes, int n_in,
                              void* d_out, int out_size)
{
    const float* x    = (const float*)d_in[0];
    const int*   mask = (const int*)  d_in[1];
    const float* cosb = (const float*)d_in[2];
    const float* sinb = (const float*)d_in[3];
    const float* Wq   = (const float*)d_in[4];
    const float* bq   = (const float*)d_in[5];
    const float* Wk   = (const float*)d_in[6];
    const float* bk   = (const float*)d_in[7];
    const float* Wv   = (const float*)d_in[8];
    const float* bv   = (const float*)d_in[9];
    const float* Wo   = (const float*)d_in[10];
    const float* bo   = (const float*)d_in[11];
    float* out = (float*)d_out;

    cudaFuncSetAttribute(attn_kernel,
                         cudaFuncAttributeMaxDynamicSharedMemorySize,
                         ATT_SMEM_BYTES);

    dim3 gemm_grid(H_ / 64, M_ / 64);   // (16, 64)
    gemm_nt<<<gemm_grid, 256>>>(x, Wq, bq, nullptr, 0);
    gemm_nt<<<gemm_grid, 256>>>(x, Wk, bk, nullptr, 1);
    gemm_nt<<<gemm_grid, 256>>>(x, Wv, bv, nullptr, 2);

    int rope_threads = B_ * NH_ * 32 * S_;          // 2,097,152
    rope_kernel<<<rope_threads / 256, 256>>>(cosb, sinb);

    dim3 attn_grid(S_ / 64, B_ * NH_);              // (32, 32)
    attn_kernel<<<attn_grid, 256, ATT_SMEM_BYTES>>>(mask);

    gemm_nt<<<gemm_grid, 256>>>(nullptr, Wo, bo, out, 3);
}

// round 5
// speedup vs baseline: 1.4464x; 1.4464x over previous
#include <cuda_runtime.h>
#include <cuda_bf16.h>
#include <math.h>
#include <stdint.h>

// Problem constants
constexpr int B_  = 2;
constexpr int S_  = 2048;
constexpr int H_  = 1024;
constexpr int NH_ = 16;
constexpr int HD_ = 64;
constexpr int M_  = B_ * S_;   // 4096
constexpr int K_  = H_;        // 1024

// ---------------- scratch (device globals; no allocation allowed) ----------
__device__ __align__(16) float g_q[(size_t)B_ * NH_ * HD_ * S_];   // [b,h,d,s]
__device__ __align__(16) float g_k[(size_t)B_ * NH_ * HD_ * S_];   // [b,h,d,s]
__device__ __align__(16) float g_v[(size_t)B_ * NH_ * S_ * HD_];   // [b,h,s,d]

// bf16 hi/lo split buffers
__device__ __align__(16) __nv_bfloat16 g_xh[(size_t)M_ * K_];
__device__ __align__(16) __nv_bfloat16 g_xl[(size_t)M_ * K_];
__device__ __align__(16) __nv_bfloat16 g_wh[4][(size_t)H_ * K_];   // q,k,v,o
__device__ __align__(16) __nv_bfloat16 g_wl[4][(size_t)H_ * K_];
__device__ __align__(16) __nv_bfloat16 g_ah[(size_t)M_ * H_];      // attention out hi
__device__ __align__(16) __nv_bfloat16 g_al[(size_t)M_ * H_];      // attention out lo

// ---------------- PTX helpers ----------------------------------------------
__device__ __forceinline__ uint32_t smem_u32(const void* p) {
    uint32_t a;
    asm("{ .reg .u64 t; cvta.to.shared.u64 t, %1; cvt.u32.u64 %0, t; }"
        : "=r"(a) : "l"(p));
    return a;
}

#define CPA16(dst, src) \
    asm volatile("cp.async.ca.shared.global [%0], [%1], 16;" \
                 :: "r"(dst), "l"(src) : "memory")
#define CP_COMMIT() asm volatile("cp.async.commit_group;" ::: "memory")
#define CP_WAIT(n)  asm volatile("cp.async.wait_group %0;" :: "n"(n) : "memory")

#define LDSM4(r, addr) \
    asm volatile("ldmatrix.sync.aligned.m8n8.x4.shared.b16 {%0,%1,%2,%3}, [%4];" \
                 : "=r"((r)[0]), "=r"((r)[1]), "=r"((r)[2]), "=r"((r)[3])        \
                 : "r"(addr))

#define MMA16816(c, a, b) \
    asm volatile("mma.sync.aligned.m16n8k16.row.col.f32.bf16.bf16.f32 "          \
                 "{%0,%1,%2,%3}, {%4,%5,%6,%7}, {%8,%9}, {%0,%1,%2,%3};"         \
                 : "+f"((c)[0]), "+f"((c)[1]), "+f"((c)[2]), "+f"((c)[3])        \
                 : "r"((a)[0]), "r"((a)[1]), "r"((a)[2]), "r"((a)[3]),           \
                   "r"((b)[0]), "r"((b)[1]))

// ---------------------------------------------------------------------------
// fp32 -> bf16 hi/lo split.  which: 0=x, 1..4=Wq..Wo
// ---------------------------------------------------------------------------
__global__ void __launch_bounds__(256) cvt_kernel(const float* __restrict__ src,
                                                  int which, int n)
{
    int i = (blockIdx.x * blockDim.x + threadIdx.x) * 4;
    if (i >= n) return;
    __nv_bfloat16 *dh, *dl;
    if (which == 0) { dh = g_xh; dl = g_xl; }
    else            { dh = g_wh[which - 1]; dl = g_wl[which - 1]; }

    float4 v = *(const float4*)(src + i);
    float vv[4] = {v.x, v.y, v.z, v.w};
    __nv_bfloat16 h[4], l[4];
#pragma unroll
    for (int j = 0; j < 4; j++) {
        h[j] = __float2bfloat16(vv[j]);
        l[j] = __float2bfloat16(vv[j] - __bfloat162float(h[j]));
    }
    *(__nv_bfloat162*)&dh[i]     = __nv_bfloat162(h[0], h[1]);
    *(__nv_bfloat162*)&dh[i + 2] = __nv_bfloat162(h[2], h[3]);
    *(__nv_bfloat162*)&dl[i]     = __nv_bfloat162(l[0], l[1]);
    *(__nv_bfloat162*)&dl[i + 2] = __nv_bfloat162(l[2], l[3]);
}

// ---------------------------------------------------------------------------
// HMMA GEMM: C[m,n] = sum_k A[m,k]*W[n,k] + bias[n], bf16 3-way split,
// fp32 accumulate. CTA tile 128x128, BK=32, 256 thr (8 warps, 2x4),
// warp tile 64x32, mma.m16n8k16, cp.async double buffer.
// mode 0: C=g_q [b,h,d,s] + RoPE     mode 1: C=g_k + RoPE
// mode 2: C=g_v [b,h,s,d]            mode 3: A=att(hi/lo), C=Cext [M,H]
// ---------------------------------------------------------------------------
constexpr int LDS_B  = 80;             // smem bytes per 32-bf16 row (padded)
constexpr int ASZ    = 128 * LDS_B;    // 10240 per operand array
constexpr int STAGE  = 4 * ASZ;        // AH, AL, WH, WL
constexpr int GEMM_SMEM = 2 * STAGE;   // 81920 (epilogue reuse: 128*132*4=67584)

__global__ void __launch_bounds__(256) hgemm(const float* __restrict__ bias,
                                             float* __restrict__ Cext,
                                             const float* __restrict__ cosb,
                                             const float* __restrict__ sinb,
                                             int mode)
{
    extern __shared__ char sm[];
    const int tid  = threadIdx.x;
    const int lane = tid & 31;
    const int wid  = tid >> 5;
    const int wm   = (wid >> 2) * 64;   // warp m offset: 0 / 64
    const int wn   = (wid & 3) * 32;    // warp n offset: 0..96
    const int n0 = blockIdx.x * 128, m0 = blockIdx.y * 128;

    const __nv_bfloat16* Ah = (mode == 3) ? g_ah : g_xh;
    const __nv_bfloat16* Al = (mode == 3) ? g_al : g_xl;
    const __nv_bfloat16* Wh = g_wh[mode];
    const __nv_bfloat16* Wl = g_wl[mode];

    const uint32_t sbase = smem_u32(sm);

    // global->smem loader: thread covers 32B of one row per operand array
    const int lr = tid >> 1;                 // row 0..127
    const size_t gA = (size_t)(m0 + lr) * K_ + (tid & 1) * 16;
    const size_t gW = (size_t)(n0 + lr) * K_ + (tid & 1) * 16;
    const uint32_t srow = (uint32_t)(lr * LDS_B + (tid & 1) * 32);

    float acc[4][4][4];
#pragma unroll
    for (int a = 0; a < 4; a++)
#pragma unroll
        for (int b = 0; b < 4; b++)
#pragma unroll
            for (int c = 0; c < 4; c++) acc[a][b][c] = 0.0f;

#define LOAD_CHUNK(ch) do {                                                   \
    const uint32_t st = sbase + ((ch) & 1) * STAGE + srow;                    \
    const char* pa = (const char*)(Ah + gA + (ch) * 32);                      \
    const char* pl = (const char*)(Al + gA + (ch) * 32);                      \
    const char* pw = (const char*)(Wh + gW + (ch) * 32);                      \
    const char* pv = (const char*)(Wl + gW + (ch) * 32);                      \
    CPA16(st,               pa); CPA16(st + 16,           pa + 16);           \
    CPA16(st + ASZ,         pl); CPA16(st + ASZ + 16,     pl + 16);           \
    CPA16(st + 2 * ASZ,     pw); CPA16(st + 2 * ASZ + 16, pw + 16);           \
    CPA16(st + 3 * ASZ,     pv); CPA16(st + 3 * ASZ + 16, pv + 16);           \
    CP_COMMIT();                                                              \
} while (0)

    LOAD_CHUNK(0);

    for (int ch = 0; ch < 32; ch++) {
        if (ch < 31) { LOAD_CHUNK(ch + 1); CP_WAIT(1); }
        else         { CP_WAIT(0); }
        __syncthreads();

        const uint32_t stg = sbase + (ch & 1) * STAGE;
#pragma unroll
        for (int ks = 0; ks < 2; ks++) {
            const int kb = ks * 32;          // byte offset of k16 step
            uint32_t aH[4][4], aL[4][4], bH[4][2], bL[4][2];
#pragma unroll
            for (int mi = 0; mi < 4; mi++) {
                uint32_t ad = stg + (uint32_t)((wm + mi * 16 + (lane & 15)) * LDS_B
                                               + kb + ((lane >> 4) << 4));
                LDSM4(aH[mi], ad);
                LDSM4(aL[mi], ad + ASZ);
            }
#pragma unroll
            for (int nh = 0; nh < 2; nh++) {
                uint32_t bd = stg + 2 * ASZ
                    + (uint32_t)((wn + nh * 16 + ((lane >> 4) << 3) + (lane & 7)) * LDS_B
                                 + kb + (((lane >> 3) & 1) << 4));
                uint32_t r[4];
                LDSM4(r, bd);
                bH[nh * 2][0] = r[0]; bH[nh * 2][1] = r[1];
                bH[nh * 2 + 1][0] = r[2]; bH[nh * 2 + 1][1] = r[3];
                LDSM4(r, bd + ASZ);
                bL[nh * 2][0] = r[0]; bL[nh * 2][1] = r[1];
                bL[nh * 2 + 1][0] = r[2]; bL[nh * 2 + 1][1] = r[3];
            }
#pragma unroll
            for (int mi = 0; mi < 4; mi++)
#pragma unroll
                for (int ni = 0; ni < 4; ni++) {
                    MMA16816(acc[mi][ni], aH[mi], bH[ni]);
                    MMA16816(acc[mi][ni], aH[mi], bL[ni]);
                    MMA16816(acc[mi][ni], aL[mi], bH[ni]);
                }
        }
        __syncthreads();
    }

    // ---- epilogue: stage C tile in smem, then fused bias (+RoPE) writeout
    constexpr int LDC = 132;   // EVEN: keeps float2/float4 accesses aligned
    float* Csm = (float*)sm;
#pragma unroll
    for (int mi = 0; mi < 4; mi++) {
        const int row = wm + mi * 16 + (lane >> 2);
#pragma unroll
        for (int ni = 0; ni < 4; ni++) {
            const int col = wn + ni * 8 + (lane & 3) * 2;
            *(float2*)&Csm[row * LDC + col] =
                make_float2(acc[mi][ni][0], acc[mi][ni][1]);
            *(float2*)&Csm[(row + 8) * LDC + col] =
                make_float2(acc[mi][ni][2], acc[mi][ni][3]);
        }
    }
    __syncthreads();

    if (mode <= 1) {
        float* C = (mode == 0) ? g_q : g_k;
#pragma unroll 4
        for (int i = 0; i < 32; i++) {
            const int id  = tid + 256 * i;       // 8192 tasks
            const int row = id & 127;            // coalesced over s
            const int pr  = (id >> 7) & 63;
            const int hh  = pr >> 5;
            const int d   = pr & 31;
            const int c0  = hh * 64 + d;
            const int m   = m0 + row;
            const int s   = m & (S_ - 1);
            const int b   = m >> 11;
            float v0 = Csm[row * LDC + c0]      + bias[n0 + c0];
            float v1 = Csm[row * LDC + c0 + 32] + bias[n0 + c0 + 32];
            const float cs0 = cosb[s * HD_ + d],      sn0 = sinb[s * HD_ + d];
            const float cs1 = cosb[s * HD_ + d + 32], sn1 = sinb[s * HD_ + d + 32];
            const int h = (n0 >> 6) + hh;
            const size_t o = ((size_t)(b * NH_ + h) * HD_ + d) * S_ + s;
            C[o]                    = v0 * cs0 - v1 * sn0;
            C[o + (size_t)32 * S_]  = v1 * cs1 + v0 * sn1;
        }
    } else {
#pragma unroll 4
        for (int i = 0; i < 16; i++) {
            const int id  = tid + 256 * i;       // 4096 float4 tasks
            const int c4  = (id & 31) * 4;
            const int row = id >> 5;
            const int m   = m0 + row;
            const int s   = m & (S_ - 1);
            const int b   = m >> 11;
            const int n   = n0 + c4;
            float4 v;
            v.x = Csm[row * LDC + c4 + 0] + bias[n + 0];
            v.y = Csm[row * LDC + c4 + 1] + bias[n + 1];
            v.z = Csm[row * LDC + c4 + 2] + bias[n + 2];
            v.w = Csm[row * LDC + c4 + 3] + bias[n + 3];
            if (mode == 2) {
                *(float4*)&g_v[((size_t)(b * NH_ + (n >> 6)) * S_ + s) * HD_ + (n & 63)] = v;
            } else {
                *(float4*)&Cext[(size_t)m * H_ + n] = v;
            }
        }
    }
}

// ---------------------------------------------------------------------------
// Flash attention, fp32 SIMT. Epilogue writes hi/lo bf16 split directly.
// ---------------------------------------------------------------------------
constexpr int ATT_SMEM_FLOATS = 64 * 64 + 64 * 68 + 64 * 64;
constexpr int ATT_SMEM_BYTES  = ATT_SMEM_FLOATS * 4;

__global__ void __launch_bounds__(256) attn_kernel(const int* __restrict__ mask)
{
    extern __shared__ float smf[];
    float* Qs = smf;
    float* KP = smf + 64 * 64;
    float* Vs = smf + 64 * 64 + 64 * 68;
    __shared__ int msk[64];

    const int tid = threadIdx.x;
    const int tx = tid & 15;
    const int ty = tid >> 4;
    const int bh = blockIdx.y;
    const int b  = bh >> 4;
    const int h  = bh & 15;
    const int q0 = blockIdx.x * 64;

    const float* Qg = g_q + (size_t)bh * HD_ * S_;
    const float* Kg = g_k + (size_t)bh * HD_ * S_;
    const float* Vg = g_v + (size_t)bh * S_ * HD_;

#pragma unroll
    for (int t = 0; t < 4; t++) {
        int lin = tid + 256 * t;
        int d = lin >> 4, sg = (lin & 15) * 4;
        *(float4*)&Qs[d * 64 + sg] = *(const float4*)&Qg[(size_t)d * S_ + q0 + sg];
    }

    float m_i[4], l_i[4], acc[4][4];
#pragma unroll
    for (int i = 0; i < 4; i++) {
        m_i[i] = -1e30f; l_i[i] = 0.0f;
#pragma unroll
        for (int j = 0; j < 4; j++) acc[i][j] = 0.0f;
    }

    for (int kt = 0; kt < S_; kt += 64) {
        __syncthreads();
#pragma unroll
        for (int t = 0; t < 4; t++) {
            int lin = tid + 256 * t;
            int r = lin >> 4, g4 = (lin & 15) * 4;
            *(float4*)&KP[r * 68 + g4] = *(const float4*)&Kg[(size_t)r * S_ + kt + g4];
            *(float4*)&Vs[r * 64 + g4] = *(const float4*)&Vg[(size_t)(kt + r) * HD_ + g4];
        }
        if (tid < 64) msk[tid] = mask[b * S_ + kt + tid];
        __syncthreads();

        float sv[4][4];
#pragma unroll
        for (int i = 0; i < 4; i++)
#pragma unroll
            for (int j = 0; j < 4; j++) sv[i][j] = 0.0f;
        for (int d = 0; d < 64; d++) {
            float a[4], bbv[4];
            *(float4*)a   = *(const float4*)&Qs[d * 64 + ty * 4];
            *(float4*)bbv = *(const float4*)&KP[d * 68 + tx * 4];
#pragma unroll
            for (int i = 0; i < 4; i++)
#pragma unroll
                for (int j = 0; j < 4; j++)
                    sv[i][j] = fmaf(a[i], bbv[j], sv[i][j]);
        }

        int mk[4];
#pragma unroll
        for (int j = 0; j < 4; j++) mk[j] = msk[tx * 4 + j];
#pragma unroll
        for (int i = 0; i < 4; i++)
#pragma unroll
            for (int j = 0; j < 4; j++) {
                float v = sv[i][j] * 0.125f;
                sv[i][j] = (mk[j] == 0) ? -1e30f : v;
            }

#pragma unroll
        for (int i = 0; i < 4; i++) {
            float rm = fmaxf(fmaxf(sv[i][0], sv[i][1]), fmaxf(sv[i][2], sv[i][3]));
#pragma unroll
            for (int off = 8; off > 0; off >>= 1)
                rm = fmaxf(rm, __shfl_xor_sync(0xffffffffu, rm, off, 16));
            float mn = fmaxf(m_i[i], rm);
            float corr = __expf(m_i[i] - mn);
            float rs = 0.0f;
#pragma unroll
            for (int j = 0; j < 4; j++) {
                float p = __expf(sv[i][j] - mn);
                sv[i][j] = p;
                rs += p;
            }
#pragma unroll
            for (int off = 8; off > 0; off >>= 1)
                rs += __shfl_xor_sync(0xffffffffu, rs, off, 16);
            l_i[i] = l_i[i] * corr + rs;
            m_i[i] = mn;
#pragma unroll
            for (int j = 0; j < 4; j++) acc[i][j] *= corr;
        }

        __syncthreads();
#pragma unroll
        for (int j = 0; j < 4; j++)
#pragma unroll
            for (int i = 0; i < 4; i++)
                KP[(tx * 4 + j) * 68 + ty * 4 + i] = sv[i][j];
        __syncthreads();

        for (int c = 0; c < 64; c++) {
            float p[4], vv[4];
            *(float4*)p  = *(const float4*)&KP[c * 68 + ty * 4];
            *(float4*)vv = *(const float4*)&Vs[c * 64 + tx * 4];
#pragma unroll
            for (int i = 0; i < 4; i++)
#pragma unroll
                for (int j = 0; j < 4; j++)
                    acc[i][j] = fmaf(p[i], vv[j], acc[i][j]);
        }
    }

    // epilogue: divide by l; write hi/lo bf16 split of attention output
#pragma unroll
    for (int i = 0; i < 4; i++) {
        const int s = q0 + ty * 4 + i;
        const float inv = 1.0f / l_i[i];
        float vv[4] = {acc[i][0] * inv, acc[i][1] * inv,
                       acc[i][2] * inv, acc[i][3] * inv};
        __nv_bfloat16 hh[4], ll[4];
#pragma unroll
        for (int j = 0; j < 4; j++) {
            hh[j] = __float2bfloat16(vv[j]);
            ll[j] = __float2bfloat16(vv[j] - __bfloat162float(hh[j]));
        }
        const size_t o = ((size_t)b * S_ + s) * H_ + h * HD_ + tx * 4;
        *(__nv_bfloat162*)&g_ah[o]     = __nv_bfloat162(hh[0], hh[1]);
        *(__nv_bfloat162*)&g_ah[o + 2] = __nv_bfloat162(hh[2], hh[3]);
        *(__nv_bfloat162*)&g_al[o]     = __nv_bfloat162(ll[0], ll[1]);
        *(__nv_bfloat162*)&g_al[o + 2] = __nv_bfloat162(ll[2], ll[3]);
    }
}

// ---------------------------------------------------------------------------
extern "C" void kernel_launch(void* const* d_in, const int* in_sizes, int n_in,
                              void* d_out, int out_size)
{
    const float* x    = (const float*)d_in[0];
    const int*   mask = (const int*)  d_in[1];
    const float* cosb = (const float*)d_in[2];
    const float* sinb = (const float*)d_in[3];
    const float* Wq   = (const float*)d_in[4];
    const float* bq   = (const float*)d_in[5];
    const float* Wk   = (const float*)d_in[6];
    const float* bk   = (const float*)d_in[7];
    const float* Wv   = (const float*)d_in[8];
    const float* bv   = (const float*)d_in[9];
    const float* Wo   = (const float*)d_in[10];
    const float* bo   = (const float*)d_in[11];
    float* out = (float*)d_out;

    cudaFuncSetAttribute(attn_kernel,
                         cudaFuncAttributeMaxDynamicSharedMemorySize,
                         ATT_SMEM_BYTES);
    cudaFuncSetAttribute(hgemm,
                         cudaFuncAttributeMaxDynamicSharedMemorySize,
                         GEMM_SMEM);

    // hi/lo conversions
    cvt_kernel<<<(M_ * K_) / 1024, 256>>>(x,  0, M_ * K_);
    cvt_kernel<<<(H_ * K_) / 1024, 256>>>(Wq, 1, H_ * K_);
    cvt_kernel<<<(H_ * K_) / 1024, 256>>>(Wk, 2, H_ * K_);
    cvt_kernel<<<(H_ * K_) / 1024, 256>>>(Wv, 3, H_ * K_);
    cvt_kernel<<<(H_ * K_) / 1024, 256>>>(Wo, 4, H_ * K_);

    dim3 gg(H_ / 128, M_ / 128);   // (8, 32)
    hgemm<<<gg, 256, GEMM_SMEM>>>(bq, nullptr, cosb, sinb, 0);  // Q + RoPE
    hgemm<<<gg, 256, GEMM_SMEM>>>(bk, nullptr, cosb, sinb, 1);  // K + RoPE
    hgemm<<<gg, 256, GEMM_SMEM>>>(bv, nullptr, cosb, sinb, 2);  // V

    dim3 ag(S_ / 64, B_ * NH_);
    attn_kernel<<<ag, 256, ATT_SMEM_BYTES>>>(mask);

    hgemm<<<gg, 256, GEMM_SMEM>>>(bo, out, cosb, sinb, 3);      // output proj
}

// round 6
// speedup vs baseline: 2.8027x; 1.9377x over previous
#include <cuda_runtime.h>
#include <cuda_bf16.h>
#include <math.h>
#include <stdint.h>

// Problem constants
constexpr int B_  = 2;
constexpr int S_  = 2048;
constexpr int H_  = 1024;
constexpr int NH_ = 16;
constexpr int HD_ = 64;
constexpr int M_  = B_ * S_;   // 4096
constexpr int K_  = H_;        // 1024

// ---------------- scratch (device globals; no allocation allowed) ----------
// Q,K stored [b,h,s,d] bf16 hi/lo (post-RoPE); V stored [b,h,d,s] bf16 hi/lo.
__device__ __align__(16) __nv_bfloat16 g_qh[(size_t)B_ * NH_ * S_ * HD_];
__device__ __align__(16) __nv_bfloat16 g_ql[(size_t)B_ * NH_ * S_ * HD_];
__device__ __align__(16) __nv_bfloat16 g_kh[(size_t)B_ * NH_ * S_ * HD_];
__device__ __align__(16) __nv_bfloat16 g_kl[(size_t)B_ * NH_ * S_ * HD_];
__device__ __align__(16) __nv_bfloat16 g_vh[(size_t)B_ * NH_ * HD_ * S_];
__device__ __align__(16) __nv_bfloat16 g_vl[(size_t)B_ * NH_ * HD_ * S_];

// bf16 hi/lo split inputs
__device__ __align__(16) __nv_bfloat16 g_xh[(size_t)M_ * K_];
__device__ __align__(16) __nv_bfloat16 g_xl[(size_t)M_ * K_];
__device__ __align__(16) __nv_bfloat16 g_wh[4][(size_t)H_ * K_];   // q,k,v,o
__device__ __align__(16) __nv_bfloat16 g_wl[4][(size_t)H_ * K_];
__device__ __align__(16) __nv_bfloat16 g_ah[(size_t)M_ * H_];      // attention out hi
__device__ __align__(16) __nv_bfloat16 g_al[(size_t)M_ * H_];      // attention out lo

// ---------------- PTX helpers ----------------------------------------------
__device__ __forceinline__ uint32_t smem_u32(const void* p) {
    uint32_t a;
    asm("{ .reg .u64 t; cvta.to.shared.u64 t, %1; cvt.u32.u64 %0, t; }"
        : "=r"(a) : "l"(p));
    return a;
}

#define CPA16(dst, src) \
    asm volatile("cp.async.ca.shared.global [%0], [%1], 16;" \
                 :: "r"(dst), "l"(src) : "memory")
#define CP_COMMIT() asm volatile("cp.async.commit_group;" ::: "memory")
#define CP_WAIT(n)  asm volatile("cp.async.wait_group %0;" :: "n"(n) : "memory")

#define LDSM4(r, addr) \
    asm volatile("ldmatrix.sync.aligned.m8n8.x4.shared.b16 {%0,%1,%2,%3}, [%4];" \
                 : "=r"((r)[0]), "=r"((r)[1]), "=r"((r)[2]), "=r"((r)[3])        \
                 : "r"(addr))

#define MMA16816(c, a, b) \
    asm volatile("mma.sync.aligned.m16n8k16.row.col.f32.bf16.bf16.f32 "          \
                 "{%0,%1,%2,%3}, {%4,%5,%6,%7}, {%8,%9}, {%0,%1,%2,%3};"         \
                 : "+f"((c)[0]), "+f"((c)[1]), "+f"((c)[2]), "+f"((c)[3])        \
                 : "r"((a)[0]), "r"((a)[1]), "r"((a)[2]), "r"((a)[3]),           \
                   "r"((b)[0]), "r"((b)[1]))

__device__ __forceinline__ uint32_t bf2pack(float a, float b) {
    __nv_bfloat162 t = __floats2bfloat162_rn(a, b);
    return *(uint32_t*)&t;
}

// ---------------------------------------------------------------------------
// fp32 -> bf16 hi/lo split.  which: 0=x, 1..4=Wq..Wo
// ---------------------------------------------------------------------------
__global__ void __launch_bounds__(256) cvt_kernel(const float* __restrict__ src,
                                                  int which, int n)
{
    int i = (blockIdx.x * blockDim.x + threadIdx.x) * 4;
    if (i >= n) return;
    __nv_bfloat16 *dh, *dl;
    if (which == 0) { dh = g_xh; dl = g_xl; }
    else            { dh = g_wh[which - 1]; dl = g_wl[which - 1]; }

    float4 v = *(const float4*)(src + i);
    float vv[4] = {v.x, v.y, v.z, v.w};
    __nv_bfloat16 h[4], l[4];
#pragma unroll
    for (int j = 0; j < 4; j++) {
        h[j] = __float2bfloat16(vv[j]);
        l[j] = __float2bfloat16(vv[j] - __bfloat162float(h[j]));
    }
    *(__nv_bfloat162*)&dh[i]     = __nv_bfloat162(h[0], h[1]);
    *(__nv_bfloat162*)&dh[i + 2] = __nv_bfloat162(h[2], h[3]);
    *(__nv_bfloat162*)&dl[i]     = __nv_bfloat162(l[0], l[1]);
    *(__nv_bfloat162*)&dl[i + 2] = __nv_bfloat162(l[2], l[3]);
}

// ---------------------------------------------------------------------------
// HMMA GEMM: C[m,n] = sum_k A[m,k]*W[n,k] + bias[n], bf16 3-way split.
// CTA 128x128, BK=32, 256 thr, warp tile 64x32, cp.async double buffer.
// mode 0: Q -> g_qh/g_ql [b,h,s,d] bf16 split, RoPE fused
// mode 1: K -> g_kh/g_kl [b,h,s,d] bf16 split, RoPE fused
// mode 2: V -> g_vh/g_vl [b,h,d,s] bf16 split
// mode 3: A=g_ah/g_al, C=Cext fp32 [M,H]
// ---------------------------------------------------------------------------
constexpr int LDS_B  = 80;             // smem bytes per 32-bf16 row (padded)
constexpr int ASZ    = 128 * LDS_B;    // 10240 per operand array
constexpr int STAGE  = 4 * ASZ;        // AH, AL, WH, WL
constexpr int GEMM_SMEM = 2 * STAGE;   // 81920 (epilogue reuse: 128*132*4=67584)

__global__ void __launch_bounds__(256) hgemm(const float* __restrict__ bias,
                                             float* __restrict__ Cext,
                                             const float* __restrict__ cosb,
                                             const float* __restrict__ sinb,
                                             int mode)
{
    extern __shared__ char sm[];
    const int tid  = threadIdx.x;
    const int lane = tid & 31;
    const int wid  = tid >> 5;
    const int wm   = (wid >> 2) * 64;
    const int wn   = (wid & 3) * 32;
    const int n0 = blockIdx.x * 128, m0 = blockIdx.y * 128;

    const __nv_bfloat16* Ah = (mode == 3) ? g_ah : g_xh;
    const __nv_bfloat16* Al = (mode == 3) ? g_al : g_xl;
    const __nv_bfloat16* Wh = g_wh[mode];
    const __nv_bfloat16* Wl = g_wl[mode];

    const uint32_t sbase = smem_u32(sm);

    const int lr = tid >> 1;
    const size_t gA = (size_t)(m0 + lr) * K_ + (tid & 1) * 16;
    const size_t gW = (size_t)(n0 + lr) * K_ + (tid & 1) * 16;
    const uint32_t srow = (uint32_t)(lr * LDS_B + (tid & 1) * 32);

    float acc[4][4][4];
#pragma unroll
    for (int a = 0; a < 4; a++)
#pragma unroll
        for (int b = 0; b < 4; b++)
#pragma unroll
            for (int c = 0; c < 4; c++) acc[a][b][c] = 0.0f;

#define LOAD_CHUNK(ch) do {                                                   \
    const uint32_t st = sbase + ((ch) & 1) * STAGE + srow;                    \
    const char* pa = (const char*)(Ah + gA + (ch) * 32);                      \
    const char* pl = (const char*)(Al + gA + (ch) * 32);                      \
    const char* pw = (const char*)(Wh + gW + (ch) * 32);                      \
    const char* pv = (const char*)(Wl + gW + (ch) * 32);                      \
    CPA16(st,               pa); CPA16(st + 16,           pa + 16);           \
    CPA16(st + ASZ,         pl); CPA16(st + ASZ + 16,     pl + 16);           \
    CPA16(st + 2 * ASZ,     pw); CPA16(st + 2 * ASZ + 16, pw + 16);           \
    CPA16(st + 3 * ASZ,     pv); CPA16(st + 3 * ASZ + 16, pv + 16);           \
    CP_COMMIT();                                                              \
} while (0)

    LOAD_CHUNK(0);

    for (int ch = 0; ch < 32; ch++) {
        if (ch < 31) { LOAD_CHUNK(ch + 1); CP_WAIT(1); }
        else         { CP_WAIT(0); }
        __syncthreads();

        const uint32_t stg = sbase + (ch & 1) * STAGE;
#pragma unroll
        for (int ks = 0; ks < 2; ks++) {
            const int kb = ks * 32;
            uint32_t aH[4][4], aL[4][4], bH[4][2], bL[4][2];
#pragma unroll
            for (int mi = 0; mi < 4; mi++) {
                uint32_t ad = stg + (uint32_t)((wm + mi * 16 + (lane & 15)) * LDS_B
                                               + kb + ((lane >> 4) << 4));
                LDSM4(aH[mi], ad);
                LDSM4(aL[mi], ad + ASZ);
            }
#pragma unroll
            for (int nh = 0; nh < 2; nh++) {
                uint32_t bd = stg + 2 * ASZ
                    + (uint32_t)((wn + nh * 16 + ((lane >> 4) << 3) + (lane & 7)) * LDS_B
                                 + kb + (((lane >> 3) & 1) << 4));
                uint32_t r[4];
                LDSM4(r, bd);
                bH[nh * 2][0] = r[0]; bH[nh * 2][1] = r[1];
                bH[nh * 2 + 1][0] = r[2]; bH[nh * 2 + 1][1] = r[3];
                LDSM4(r, bd + ASZ);
                bL[nh * 2][0] = r[0]; bL[nh * 2][1] = r[1];
                bL[nh * 2 + 1][0] = r[2]; bL[nh * 2 + 1][1] = r[3];
            }
#pragma unroll
            for (int mi = 0; mi < 4; mi++)
#pragma unroll
                for (int ni = 0; ni < 4; ni++) {
                    MMA16816(acc[mi][ni], aH[mi], bH[ni]);
                    MMA16816(acc[mi][ni], aH[mi], bL[ni]);
                    MMA16816(acc[mi][ni], aL[mi], bH[ni]);
                }
        }
        __syncthreads();
    }

    // ---- epilogue: stage C tile in smem, then fused writeout
    constexpr int LDC = 132;   // even: float2/float4 stay aligned
    float* Csm = (float*)sm;
#pragma unroll
    for (int mi = 0; mi < 4; mi++) {
        const int row = wm + mi * 16 + (lane >> 2);
#pragma unroll
        for (int ni = 0; ni < 4; ni++) {
            const int col = wn + ni * 8 + (lane & 3) * 2;
            *(float2*)&Csm[row * LDC + col] =
                make_float2(acc[mi][ni][0], acc[mi][ni][1]);
            *(float2*)&Csm[(row + 8) * LDC + col] =
                make_float2(acc[mi][ni][2], acc[mi][ni][3]);
        }
    }
    __syncthreads();

    if (mode <= 1) {
        // RoPE + bf16 hi/lo split -> [b,h,s,d]
        __nv_bfloat16* Ch = (mode == 0) ? g_qh : g_kh;
        __nv_bfloat16* Cl = (mode == 0) ? g_ql : g_kl;
#pragma unroll 2
        for (int i = 0; i < 16; i++) {
            const int id  = tid + 256 * i;        // 4096 tasks
            const int dp  = id & 15;              // d pair 0..15
            const int hh  = (id >> 4) & 1;
            const int row = id >> 5;
            const int d0  = dp * 2;
            const int m   = m0 + row;
            const int s   = m & (S_ - 1);
            const int bb  = m >> 11;
            float oA[2], oB[2];
#pragma unroll
            for (int e = 0; e < 2; e++) {
                const int d = d0 + e, c = hh * 64 + d;
                const float v0 = Csm[row * LDC + c]      + bias[n0 + c];
                const float v1 = Csm[row * LDC + c + 32] + bias[n0 + c + 32];
                const float cs0 = cosb[s * HD_ + d],      sn0 = sinb[s * HD_ + d];
                const float cs1 = cosb[s * HD_ + d + 32], sn1 = sinb[s * HD_ + d + 32];
                oA[e] = v0 * cs0 - v1 * sn0;     // value at d
                oB[e] = v1 * cs1 + v0 * sn1;     // value at d+32
            }
            const int hidx = (n0 >> 6) + hh;
            const size_t base = ((size_t)(bb * NH_ + hidx) * S_ + s) * HD_;
            const __nv_bfloat16 a0 = __float2bfloat16(oA[0]);
            const __nv_bfloat16 a1 = __float2bfloat16(oA[1]);
            const __nv_bfloat16 c0 = __float2bfloat16(oB[0]);
            const __nv_bfloat16 c1 = __float2bfloat16(oB[1]);
            *(__nv_bfloat162*)&Ch[base + d0]      = __nv_bfloat162(a0, a1);
            *(__nv_bfloat162*)&Ch[base + d0 + 32] = __nv_bfloat162(c0, c1);
            *(__nv_bfloat162*)&Cl[base + d0] = __nv_bfloat162(
                __float2bfloat16(oA[0] - __bfloat162float(a0)),
                __float2bfloat16(oA[1] - __bfloat162float(a1)));
            *(__nv_bfloat162*)&Cl[base + d0 + 32] = __nv_bfloat162(
                __float2bfloat16(oB[0] - __bfloat162float(c0)),
                __float2bfloat16(oB[1] - __bfloat162float(c1)));
        }
    } else if (mode == 2) {
        // bf16 hi/lo split -> [b,h,d,s]
#pragma unroll 2
        for (int i = 0; i < 32; i++) {
            const int id  = tid + 256 * i;        // 8192 tasks
            const int sp  = id & 63;              // s pair
            const int c   = id >> 6;              // 0..127
            const int row0 = sp * 2;
            const int m   = m0 + row0;
            const int s   = m & (S_ - 1);
            const int bb  = m >> 11;
            const int n   = n0 + c;
            const int hidx = n >> 6, d = n & 63;
            const float v0 = Csm[row0 * LDC + c]       + bias[n];
            const float v1 = Csm[(row0 + 1) * LDC + c] + bias[n];
            const __nv_bfloat16 h0 = __float2bfloat16(v0);
            const __nv_bfloat16 h1 = __float2bfloat16(v1);
            const size_t o = ((size_t)(bb * NH_ + hidx) * HD_ + d) * S_ + s;
            *(__nv_bfloat162*)&g_vh[o] = __nv_bfloat162(h0, h1);
            *(__nv_bfloat162*)&g_vl[o] = __nv_bfloat162(
                __float2bfloat16(v0 - __bfloat162float(h0)),
                __float2bfloat16(v1 - __bfloat162float(h1)));
        }
    } else {
#pragma unroll 4
        for (int i = 0; i < 16; i++) {
            const int id  = tid + 256 * i;
            const int c4  = (id & 31) * 4;
            const int row = id >> 5;
            const int m   = m0 + row;
            const int n   = n0 + c4;
            float4 v;
            v.x = Csm[row * LDC + c4 + 0] + bias[n + 0];
            v.y = Csm[row * LDC + c4 + 1] + bias[n + 1];
            v.z = Csm[row * LDC + c4 + 2] + bias[n + 2];
            v.w = Csm[row * LDC + c4 + 3] + bias[n + 3];
            *(float4*)&Cext[(size_t)m * H_ + n] = v;
        }
    }
}

// ---------------------------------------------------------------------------
// Flash attention, HMMA bf16 3-way split, fp32 softmax on fragments.
// Block: one (b,h) x 128-row Q tile. 8 warps (16 q rows each). KV tile 64,
// cp.async double-buffered. Q/K [s][d] hi/lo; V [d][s] hi/lo.
// ---------------------------------------------------------------------------
constexpr int LDSA     = 144;                 // bytes per 64-bf16 row (+16 pad)
constexpr int QBYTES   = 2 * 128 * LDSA;      // 36864 (Qh | Ql)
constexpr int KVSTAGE  = 4 * 64 * LDSA;       // 36864 (Kh|Kl|Vh|Vl)
constexpr int ATT2_SMEM = QBYTES + 2 * KVSTAGE; // 110592

__global__ void __launch_bounds__(256) attn_hmma(const int* __restrict__ mask)
{
    extern __shared__ char sm[];
    const uint32_t sb = smem_u32(sm);
    __shared__ int msk[2][64];

    const int tid = threadIdx.x, lane = tid & 31, w = tid >> 5;
    const int bh = blockIdx.y, b = bh >> 4, h = bh & 15;
    const int q0 = blockIdx.x * 128;

    const __nv_bfloat16* Qhp = g_qh + (size_t)bh * S_ * HD_;
    const __nv_bfloat16* Qlp = g_ql + (size_t)bh * S_ * HD_;
    const __nv_bfloat16* Khp = g_kh + (size_t)bh * S_ * HD_;
    const __nv_bfloat16* Klp = g_kl + (size_t)bh * S_ * HD_;
    const __nv_bfloat16* Vhp = g_vh + (size_t)bh * HD_ * S_;
    const __nv_bfloat16* Vlp = g_vl + (size_t)bh * HD_ * S_;
    const int* maskp = mask + b * S_;

    // Q tile load (rows [q0, q0+128), hi+lo)
#pragma unroll
    for (int i = 0; i < 4; i++) {
        const int idx = tid + 256 * i;          // 1024
        const int row = idx >> 3, chk = idx & 7;
        const uint32_t dst = sb + (uint32_t)(row * LDSA + chk * 16);
        CPA16(dst,         (const char*)(Qhp + (size_t)(q0 + row) * HD_ + chk * 8));
        CPA16(dst + 18432, (const char*)(Qlp + (size_t)(q0 + row) * HD_ + chk * 8));
    }

#define LOADKV(t) do {                                                          \
    const int kt_ = (t) * 64;                                                   \
    const uint32_t st = sb + QBYTES + ((t) & 1) * KVSTAGE;                      \
    _Pragma("unroll")                                                           \
    for (int i_ = 0; i_ < 2; i_++) {                                            \
        const int idx_ = tid + 256 * i_;                                        \
        const int row_ = idx_ >> 3, ch_ = idx_ & 7;                             \
        const uint32_t ro_ = (uint32_t)(row_ * LDSA + ch_ * 16);                \
        CPA16(st + ro_,          (const char*)(Khp + (size_t)(kt_ + row_) * HD_ + ch_ * 8)); \
        CPA16(st + 9216 + ro_,   (const char*)(Klp + (size_t)(kt_ + row_) * HD_ + ch_ * 8)); \
        CPA16(st + 18432 + ro_,  (const char*)(Vhp + (size_t)row_ * S_ + kt_ + ch_ * 8));    \
        CPA16(st + 27648 + ro_,  (const char*)(Vlp + (size_t)row_ * S_ + kt_ + ch_ * 8));    \
    }                                                                           \
    if (tid < 64) msk[(t) & 1][tid] = maskp[kt_ + tid];                         \
    CP_COMMIT();                                                                \
} while (0)

    LOADKV(0);   // group 0 also carries the Q loads

    float m_[2] = {-1e30f, -1e30f}, l_[2] = {0.0f, 0.0f};
    float oacc[8][4];
#pragma unroll
    for (int n = 0; n < 8; n++)
#pragma unroll
        for (int j = 0; j < 4; j++) oacc[n][j] = 0.0f;

    const int c01 = (lane & 3) * 2;

    for (int t = 0; t < S_ / 64; t++) {
        if (t < S_ / 64 - 1) { LOADKV(t + 1); CP_WAIT(1); }
        else                 { CP_WAIT(0); }
        __syncthreads();

        const uint32_t kst = sb + QBYTES + (t & 1) * KVSTAGE;

        // ---- S = Q K^T (3-way split) ----
        float sacc[8][4];
#pragma unroll
        for (int n = 0; n < 8; n++)
#pragma unroll
            for (int j = 0; j < 4; j++) sacc[n][j] = 0.0f;

#pragma unroll
        for (int kk = 0; kk < 4; kk++) {
            uint32_t aH[4], aL[4];
            const uint32_t ad = sb + (uint32_t)((w * 16 + (lane & 15)) * LDSA
                                                + kk * 32 + ((lane >> 4) << 4));
            LDSM4(aH, ad);
            LDSM4(aL, ad + 18432);
#pragma unroll
            for (int nh = 0; nh < 4; nh++) {
                const uint32_t bd = kst
                    + (uint32_t)((nh * 16 + ((lane >> 4) << 3) + (lane & 7)) * LDSA
                                 + kk * 32 + (((lane >> 3) & 1) << 4));
                uint32_t rh[4], rl[4];
                LDSM4(rh, bd);
                LDSM4(rl, bd + 9216);
                uint32_t b0[2] = {rh[0], rh[1]}, b1[2] = {rh[2], rh[3]};
                uint32_t d0[2] = {rl[0], rl[1]}, d1[2] = {rl[2], rl[3]};
                MMA16816(sacc[nh * 2],     aH, b0);
                MMA16816(sacc[nh * 2],     aH, d0);
                MMA16816(sacc[nh * 2],     aL, b0);
                MMA16816(sacc[nh * 2 + 1], aH, b1);
                MMA16816(sacc[nh * 2 + 1], aH, d1);
                MMA16816(sacc[nh * 2 + 1], aL, b1);
            }
        }

        // ---- scale + mask + online softmax ----
        float mx[2] = {-1e30f, -1e30f};
#pragma unroll
        for (int n = 0; n < 8; n++) {
            const int cc = n * 8 + c01;
            const int mk0 = msk[t & 1][cc], mk1 = msk[t & 1][cc + 1];
#pragma unroll
            for (int j = 0; j < 4; j++) {
                float v = sacc[n][j] * 0.125f;
                v = ((j & 1) ? mk1 : mk0) ? v : -1e30f;
                sacc[n][j] = v;
                mx[j >> 1] = fmaxf(mx[j >> 1], v);
            }
        }
        float corr[2], rs[2] = {0.0f, 0.0f};
#pragma unroll
        for (int r = 0; r < 2; r++) {
            mx[r] = fmaxf(mx[r], __shfl_xor_sync(0xffffffffu, mx[r], 1, 4));
            mx[r] = fmaxf(mx[r], __shfl_xor_sync(0xffffffffu, mx[r], 2, 4));
            const float mn = fmaxf(m_[r], mx[r]);
            corr[r] = __expf(m_[r] - mn);
            m_[r] = mn;
        }
#pragma unroll
        for (int n = 0; n < 8; n++)
#pragma unroll
            for (int j = 0; j < 4; j++) {
                const float p = __expf(sacc[n][j] - m_[j >> 1]);
                sacc[n][j] = p;
                rs[j >> 1] += p;
            }
#pragma unroll
        for (int r = 0; r < 2; r++) {
            rs[r] += __shfl_xor_sync(0xffffffffu, rs[r], 1, 4);
            rs[r] += __shfl_xor_sync(0xffffffffu, rs[r], 2, 4);
            l_[r] = l_[r] * corr[r] + rs[r];
        }
#pragma unroll
        for (int n = 0; n < 8; n++)
#pragma unroll
            for (int j = 0; j < 4; j++) oacc[n][j] *= corr[j >> 1];

        // ---- O += P V (P split in registers; V [d][kv] hi/lo) ----
#pragma unroll
        for (int j = 0; j < 4; j++) {          // k16 step over kv
            uint32_t aPh[4], aPl[4];
#pragma unroll
            for (int half = 0; half < 2; half++) {
                const float p0 = sacc[2 * j + half][0];
                const float p1 = sacc[2 * j + half][1];
                const float p2 = sacc[2 * j + half][2];
                const float p3 = sacc[2 * j + half][3];
                const float q0f = __bfloat162float(__float2bfloat16(p0));
                const float q1f = __bfloat162float(__float2bfloat16(p1));
                const float q2f = __bfloat162float(__float2bfloat16(p2));
                const float q3f = __bfloat162float(__float2bfloat16(p3));
                aPh[half * 2]     = bf2pack(p0, p1);
                aPh[half * 2 + 1] = bf2pack(p2, p3);
                aPl[half * 2]     = bf2pack(p0 - q0f, p1 - q1f);
                aPl[half * 2 + 1] = bf2pack(p2 - q2f, p3 - q3f);
            }
#pragma unroll
            for (int nh = 0; nh < 4; nh++) {
                const uint32_t bd = kst + 18432
                    + (uint32_t)((nh * 16 + ((lane >> 4) << 3) + (lane & 7)) * LDSA
                                 + j * 32 + (((lane >> 3) & 1) << 4));
                uint32_t rh[4], rl[4];
                LDSM4(rh, bd);
                LDSM4(rl, bd + 9216);
                uint32_t b0[2] = {rh[0], rh[1]}, b1[2] = {rh[2], rh[3]};
                uint32_t d0[2] = {rl[0], rl[1]}, d1[2] = {rl[2], rl[3]};
                MMA16816(oacc[nh * 2],     aPh, b0);
                MMA16816(oacc[nh * 2],     aPh, d0);
                MMA16816(oacc[nh * 2],     aPl, b0);
                MMA16816(oacc[nh * 2 + 1], aPh, b1);
                MMA16816(oacc[nh * 2 + 1], aPh, d1);
                MMA16816(oacc[nh * 2 + 1], aPl, b1);
            }
        }
        __syncthreads();
    }

    // ---- epilogue: /l, write hi/lo bf16 to g_ah/g_al [M,H] ----
    const int r0 = lane >> 2;
#pragma unroll
    for (int r = 0; r < 2; r++) {
        const float inv = 1.0f / l_[r];
        const int srow = q0 + w * 16 + r0 + 8 * r;
        const size_t base = ((size_t)b * S_ + srow) * H_ + h * 64 + c01;
#pragma unroll
        for (int n = 0; n < 8; n++) {
            const float v0 = oacc[n][2 * r]     * inv;
            const float v1 = oacc[n][2 * r + 1] * inv;
            const __nv_bfloat16 h0 = __float2bfloat16(v0);
            const __nv_bfloat16 h1 = __float2bfloat16(v1);
            *(__nv_bfloat162*)&g_ah[base + n * 8] = __nv_bfloat162(h0, h1);
            *(__nv_bfloat162*)&g_al[base + n * 8] = __nv_bfloat162(
                __float2bfloat16(v0 - __bfloat162float(h0)),
                __float2bfloat16(v1 - __bfloat162float(h1)));
        }
    }
}

// ---------------------------------------------------------------------------
extern "C" void kernel_launch(void* const* d_in, const int* in_sizes, int n_in,
                              void* d_out, int out_size)
{
    const float* x    = (const float*)d_in[0];
    const int*   mask = (const int*)  d_in[1];
    const float* cosb = (const float*)d_in[2];
    const float* sinb = (const float*)d_in[3];
    const float* Wq   = (const float*)d_in[4];
    const float* bq   = (const float*)d_in[5];
    const float* Wk   = (const float*)d_in[6];
    const float* bk   = (const float*)d_in[7];
    const float* Wv   = (const float*)d_in[8];
    const float* bv   = (const float*)d_in[9];
    const float* Wo   = (const float*)d_in[10];
    const float* bo   = (const float*)d_in[11];
    float* out = (float*)d_out;

    cudaFuncSetAttribute(hgemm,
                         cudaFuncAttributeMaxDynamicSharedMemorySize, GEMM_SMEM);
    cudaFuncSetAttribute(attn_hmma,
                         cudaFuncAttributeMaxDynamicSharedMemorySize, ATT2_SMEM);

    cvt_kernel<<<(M_ * K_) / 1024, 256>>>(x,  0, M_ * K_);
    cvt_kernel<<<(H_ * K_) / 1024, 256>>>(Wq, 1, H_ * K_);
    cvt_kernel<<<(H_ * K_) / 1024, 256>>>(Wk, 2, H_ * K_);
    cvt_kernel<<<(H_ * K_) / 1024, 256>>>(Wv, 3, H_ * K_);
    cvt_kernel<<<(H_ * K_) / 1024, 256>>>(Wo, 4, H_ * K_);

    dim3 gg(H_ / 128, M_ / 128);   // (8, 32)
    hgemm<<<gg, 256, GEMM_SMEM>>>(bq, nullptr, cosb, sinb, 0);  // Q + RoPE
    hgemm<<<gg, 256, GEMM_SMEM>>>(bk, nullptr, cosb, sinb, 1);  // K + RoPE
    hgemm<<<gg, 256, GEMM_SMEM>>>(bv, nullptr, cosb, sinb, 2);  // V

    dim3 ag(S_ / 128, B_ * NH_);   // (16, 32)
    attn_hmma<<<ag, 256, ATT2_SMEM>>>(mask);

    hgemm<<<gg, 256, GEMM_SMEM>>>(bo, out, cosb, sinb, 3);      // output proj
}